// round 8
// baseline (speedup 1.0000x reference)
#include <cuda_runtime.h>
#include <math.h>

#define BB 16
#define FF 2048
#define SS 512
#define DD 256
#define DH 512
#define NSEG (BB*SS)      // 8192
#define NEDGE (BB*FF)     // 32768
#define DLAT 512
#define NB 148            // co-resident blocks (<= SM count)
#define NT 256

typedef unsigned long long ull;

// ---- scratch (static __device__ arrays; no allocations allowed) ----
__device__ __align__(16) float g_P[2*SS*DH];     // [0]=pos@W1a, [1]=pos@W1c
__device__ __align__(16) float g_Eb[8*DH];       // pred_emb @ W1b
__device__ __align__(16) float g_Rc[8*DH];       // role_emb @ W1c
__device__ __align__(16) float g_H[NSEG*DH];     // per-node hidden sums
__device__ __align__(16) float g_agg[NSEG*DD];   // H @ W2
__device__ float g_pooled[BB*DD];
__device__ __align__(16) int g_cnt[NSEG];
__device__ int   g_off[NSEG];
__device__ int   g_run[NSEG];
__device__ unsigned g_perm[2*NEDGE];
// grid barrier state (monotonic tickets; never reset -> replay-safe)
__device__ unsigned g_arrive_ctr = 0;
__device__ unsigned g_release_ctr = 0;

__device__ __forceinline__ float gelu_f(float x){
    return 0.5f*x*(1.0f + erff(x*0.70710678118654752440f));
}
__device__ __forceinline__ void ffma2(ull &d, ull a, ull b){
    asm("fma.rn.f32x2 %0, %1, %2, %0;" : "+l"(d) : "l"(a), "l"(b));
}
__device__ __forceinline__ ull pack2(float x){
    ull r; asm("mov.b64 %0, {%1, %1};" : "=l"(r) : "f"(x)); return r;
}
__device__ __forceinline__ void unpack2(float &lo, float &hi, ull v){
    asm("mov.b64 {%0, %1}, %2;" : "=f"(lo), "=f"(hi) : "l"(v));
}

// ---- software grid barrier (all NB blocks co-resident) ----
__device__ __forceinline__ void gsync(){
    __threadfence();                 // release my writes (gpu scope)
    __syncthreads();
    if (threadIdx.x == 0){
        unsigned t = atomicAdd(&g_arrive_ctr, 1u) + 1u;
        if ((t % NB) == 0u){
            atomicAdd(&g_release_ctr, 1u);
        } else {
            unsigned target = (t + NB - 1u) / NB;
            volatile unsigned* rel = &g_release_ctr;
            while (*rel < target) { __nanosleep(64); }
        }
    }
    __syncthreads();
    __threadfence();                 // acquire: invalidate L1D (CCTL.IVALL on sm_103a)
}

struct SmGemm { float As[2][16][132]; float Bs[2][16][128]; };  // 33280 B

__global__ __launch_bounds__(NT, 1)
void k_fused(const int* __restrict__ a0, const int* __restrict__ a1,
             const int* __restrict__ pidx, const int* __restrict__ ridx,
             const float* __restrict__ pos, const float* __restrict__ pre,
             const float* __restrict__ rol,
             const float* __restrict__ W1, const float* __restrict__ b1,
             const float* __restrict__ W2, const float* __restrict__ b2,
             const float* __restrict__ lng, const float* __restrict__ lnb,
             const float* __restrict__ Wl1, const float* __restrict__ bl1,
             const float* __restrict__ Wl2, const float* __restrict__ bl2,
             float* __restrict__ out){
    __shared__ __align__(16) char smr[sizeof(SmGemm)];
    int blk = blockIdx.x, tid = threadIdx.x;
    int gid = blk*NT + tid;

    // ---------- Phase A: zero cnt + pooled ----------
    for (int i = gid; i < NSEG; i += NB*NT) g_cnt[i] = 0;
    if (gid < BB*DD) g_pooled[gid] = 0.f;
    gsync();

    // ---------- Phase B: count messages per destination ----------
    for (int e = gid; e < NEDGE; e += NB*NT){
        int b = e >> 11;
        int v0 = a0[e], v1 = a1[e], p = pidx[e];
        bool role = (p == 1);
        int dstf = role ? v0 : v1;
        atomicAdd(&g_cnt[b*SS + dstf], 1);
        if (!role && p != 0) atomicAdd(&g_cnt[b*SS + v0], 1);
    }
    gsync();

    // ---------- Phase C: scan (block 0)  ||  precompute tables (blocks 1..147) ----------
    if (blk == 0){
        // two-pass exclusive scan of 8192 counts: 256 thr x 32 elems
        int base = tid*32;
        int s = 0;
        #pragma unroll 8
        for (int i=0;i<32;i++) s += g_cnt[base+i];
        int lane = tid&31, warp = tid>>5;
        int x = s;
        #pragma unroll
        for (int o=1;o<32;o<<=1){ int y=__shfl_up_sync(0xffffffffu,x,o); if(lane>=o) x+=y; }
        int* wsum = (int*)smr;
        if (lane==31) wsum[warp] = x;
        __syncthreads();
        int wb = 0;
        for (int w=0; w<warp; w++) wb += wsum[w];
        int run = x - s + wb;
        #pragma unroll 8
        for (int i=0;i<32;i++){
            g_off[base+i] = run; g_run[base+i] = run;
            run += g_cnt[base+i];
        }
    } else {
        int w = blk - 1;                    // 147 workers, 144 items
        if (w < 128){
            // pos precompute tile: 64x64, C[z] = pos @ W1slice
            int nx = w&7, my = (w>>3)&7, z = w>>6;
            const float* Bm = W1 + (z ? (size_t)2*DD*DH : 0);
            float* C = g_P + (size_t)z * SS*DH;
            float (*As)[68] = (float(*)[68])smr;
            float (*Bs)[64] = (float(*)[64])(smr + 16*68*4);
            int bm = my*64, bn = nx*64;
            int tx = tid & 15, ty = tid >> 4;
            int la_k = tid & 15, la_m = (tid >> 4)*4;
            int lb_n = tid & 63, lb_k = (tid >> 6)*4;
            float acc[4][4] = {};
            for (int k0=0;k0<DD;k0+=16){
                #pragma unroll
                for (int i=0;i<4;i++) As[la_k][la_m+i] = pos[(size_t)(bm+la_m+i)*DD + k0 + la_k];
                #pragma unroll
                for (int i=0;i<4;i++) Bs[lb_k+i][lb_n] = Bm[(size_t)(k0+lb_k+i)*DH + bn + lb_n];
                __syncthreads();
                #pragma unroll
                for (int k=0;k<16;k++){
                    float av[4], bv[4];
                    #pragma unroll
                    for (int i=0;i<4;i++) av[i]=As[k][ty*4+i];
                    #pragma unroll
                    for (int j=0;j<4;j++) bv[j]=Bs[k][tx*4+j];
                    #pragma unroll
                    for (int i=0;i<4;i++)
                        #pragma unroll
                        for (int j=0;j<4;j++) acc[i][j] += av[i]*bv[j];
                }
                __syncthreads();
            }
            #pragma unroll
            for (int i=0;i<4;i++)
                #pragma unroll
                for (int j=0;j<4;j++)
                    C[(size_t)(bm+ty*4+i)*DH + bn+tx*4+j] = acc[i][j];
        } else if (w < 144){
            // small table row: pred/role @ W1 slice
            int r8 = w - 128;
            const float* A; const float* W; float* C; int r;
            if (r8 < 8){ A=pre; W=W1+DD*DH;   C=g_Eb; r=r8; }
            else       { A=rol; W=W1+2*DD*DH; C=g_Rc; r=r8-8; }
            float* a = (float*)smr;
            if (tid < DD) a[tid] = A[r*DD + tid];
            __syncthreads();
            for (int j=tid; j<DH; j+=NT){
                float s = 0.f;
                #pragma unroll 4
                for (int k=0;k<DD;k++) s += a[k]*W[(size_t)k*DH + j];
                C[r*DH + j] = s;
            }
        }
    }
    gsync();

    // ---------- Phase D: place descriptors into CSR slots ----------
    for (int e = gid; e < NEDGE; e += NB*NT){
        int b = e >> 11;
        int v0=a0[e], v1=a1[e], p=pidx[e];
        bool role = (p==1);
        unsigned descf; int dstf;
        if (role){ dstf=v0; descf=(unsigned)v0 | ((unsigned)(ridx[e]+1)<<10) | ((unsigned)p<<20) | (1u<<23); }
        else     { dstf=v1; descf=(unsigned)v0 | ((unsigned)v1<<10)          | ((unsigned)p<<20); }
        int slot = atomicAdd(&g_run[b*SS+dstf],1);
        g_perm[slot]=descf;
        if (!role && p!=0){
            unsigned descb = (unsigned)v1 | ((unsigned)v0<<10) | ((unsigned)p<<20);
            slot = atomicAdd(&g_run[b*SS+v0],1);
            g_perm[slot]=descb;
        }
    }
    gsync();

    // ---------- Phase E: per-node gather (2 nodes per block-iteration) ----------
    {
        int sub = tid >> 7;                // 0/1: node within pair (warp-aligned)
        int wg  = tid & 127;
        const float4* PA = reinterpret_cast<const float4*>(g_P);
        const float4* PC = PA + SS*DH/4;
        const float4* EB = reinterpret_cast<const float4*>(g_Eb);
        const float4* RC = reinterpret_cast<const float4*>(g_Rc);
        float4 b1v = reinterpret_cast<const float4*>(b1)[wg];
        for (int pr = blk; pr < NSEG/2; pr += NB){
            int node = pr*2 + sub;
            int start = g_off[node];
            int cnt = g_cnt[node];
            float4 acc = make_float4(0.f,0.f,0.f,0.f);
            for (int m=0;m<cnt;m++){
                unsigned d = g_perm[start+m];
                int iA = d & 1023, iC = (d>>10)&1023, p = (d>>20)&7;
                const float4* T = (d & (1u<<23)) ? RC : PC;
                float4 a = PA[iA*128 + wg];
                float4 c = T [iC*128 + wg];
                float4 e = EB[p *128 + wg];
                acc.x += gelu_f(a.x+c.x+e.x+b1v.x);
                acc.y += gelu_f(a.y+c.y+e.y+b1v.y);
                acc.z += gelu_f(a.z+c.z+e.z+b1v.z);
                acc.w += gelu_f(a.w+c.w+e.w+b1v.w);
            }
            reinterpret_cast<float4*>(g_H)[node*128 + wg] = acc;
        }
    }
    gsync();

    // ---------- Phase F: agg = H @ W2  (128x128 FFMA2 tiles; 128 of 148 blocks) ----------
    if (blk < 128){
        SmGemm* sg = (SmGemm*)smr;
        const float* A = g_H; const float* B = W2; float* C = g_agg;
        const int N = DD, K = DH;
        int bm = (blk>>1)*128, bn = (blk&1)*128;
        int tx = tid & 15, ty = tid >> 4;

        int aidx0 = tid*2, aidx1 = tid*2+1;
        int ar0 = aidx0>>2, ac0 = aidx0&3;
        int ar1 = aidx1>>2, ac1 = aidx1&3;
        int br0 = aidx0>>5, bc0 = aidx0&31;
        int br1 = aidx1>>5, bc1 = aidx1&31;

        float4 pa0, pa1, pb0, pb1;
        pa0 = *reinterpret_cast<const float4*>(&A[(size_t)(bm+ar0)*K + ac0*4]);
        pa1 = *reinterpret_cast<const float4*>(&A[(size_t)(bm+ar1)*K + ac1*4]);
        pb0 = *reinterpret_cast<const float4*>(&B[(size_t)(br0)*N + bn + bc0*4]);
        pb1 = *reinterpret_cast<const float4*>(&B[(size_t)(br1)*N + bn + bc1*4]);

        ull acc2[4][8];
        #pragma unroll
        for (int i=0;i<4;i++)
            #pragma unroll
            for (int j=0;j<8;j++) acc2[i][j]=0ull;

        int buf = 0;
        sg->As[0][ac0*4+0][ar0]=pa0.x; sg->As[0][ac0*4+1][ar0]=pa0.y; sg->As[0][ac0*4+2][ar0]=pa0.z; sg->As[0][ac0*4+3][ar0]=pa0.w;
        sg->As[0][ac1*4+0][ar1]=pa1.x; sg->As[0][ac1*4+1][ar1]=pa1.y; sg->As[0][ac1*4+2][ar1]=pa1.z; sg->As[0][ac1*4+3][ar1]=pa1.w;
        *reinterpret_cast<float4*>(&sg->Bs[0][br0][bc0*4]) = pb0;
        *reinterpret_cast<float4*>(&sg->Bs[0][br1][bc1*4]) = pb1;
        __syncthreads();

        const int ktiles = K/16;
        for (int kt=0; kt<ktiles; kt++){
            bool more = (kt+1 < ktiles);
            if (more){
                int kk = (kt+1)*16;
                pa0 = *reinterpret_cast<const float4*>(&A[(size_t)(bm+ar0)*K + kk + ac0*4]);
                pa1 = *reinterpret_cast<const float4*>(&A[(size_t)(bm+ar1)*K + kk + ac1*4]);
                pb0 = *reinterpret_cast<const float4*>(&B[(size_t)(kk+br0)*N + bn + bc0*4]);
                pb1 = *reinterpret_cast<const float4*>(&B[(size_t)(kk+br1)*N + bn + bc1*4]);
            }
            #pragma unroll
            for (int k=0;k<16;k++){
                const ull* a64 = reinterpret_cast<const ull*>(&sg->As[buf][k][ty*8]);
                ull ap0=a64[0], ap1=a64[1], ap2=a64[2], ap3=a64[3];
                const float4* b4 = reinterpret_cast<const float4*>(&sg->Bs[buf][k][tx*8]);
                float4 b0 = b4[0], b1r = b4[1];
                float bv[8] = {b0.x,b0.y,b0.z,b0.w,b1r.x,b1r.y,b1r.z,b1r.w};
                #pragma unroll
                for (int j=0;j<8;j++){
                    ull bb = pack2(bv[j]);
                    ffma2(acc2[0][j], ap0, bb);
                    ffma2(acc2[1][j], ap1, bb);
                    ffma2(acc2[2][j], ap2, bb);
                    ffma2(acc2[3][j], ap3, bb);
                }
            }
            if (more){
                buf ^= 1;
                sg->As[buf][ac0*4+0][ar0]=pa0.x; sg->As[buf][ac0*4+1][ar0]=pa0.y; sg->As[buf][ac0*4+2][ar0]=pa0.z; sg->As[buf][ac0*4+3][ar0]=pa0.w;
                sg->As[buf][ac1*4+0][ar1]=pa1.x; sg->As[buf][ac1*4+1][ar1]=pa1.y; sg->As[buf][ac1*4+2][ar1]=pa1.z; sg->As[buf][ac1*4+3][ar1]=pa1.w;
                *reinterpret_cast<float4*>(&sg->Bs[buf][br0][bc0*4]) = pb0;
                *reinterpret_cast<float4*>(&sg->Bs[buf][br1][bc1*4]) = pb1;
                __syncthreads();
            }
        }
        #pragma unroll
        for (int i2=0;i2<4;i2++){
            float lo[8], hi[8];
            #pragma unroll
            for (int j=0;j<8;j++) unpack2(lo[j], hi[j], acc2[i2][j]);
            size_t r0 = (size_t)(bm + ty*8 + i2*2)*N + bn + tx*8;
            size_t r1 = r0 + N;
            reinterpret_cast<float4*>(&C[r0])[0] = make_float4(lo[0],lo[1],lo[2],lo[3]);
            reinterpret_cast<float4*>(&C[r0])[1] = make_float4(lo[4],lo[5],lo[6],lo[7]);
            reinterpret_cast<float4*>(&C[r1])[0] = make_float4(hi[0],hi[1],hi[2],hi[3]);
            reinterpret_cast<float4*>(&C[r1])[1] = make_float4(hi[4],hi[5],hi[6],hi[7]);
        }
    }
    gsync();

    // ---------- Phase G: LN + pooled accumulation (128 of 148 blocks) ----------
    if (blk < 128){
        int bIdx = blk >> 3;
        int r0 = (blk & 7)*64;
        int warp = tid>>5, lane = tid&31;
        float accp[8];
        #pragma unroll
        for (int i=0;i<8;i++) accp[i]=0.f;
        for (int rr=warp; rr<64; rr+=8){
            int s = r0+rr;
            int seg = bIdx*SS + s;
            float cntf = (float)g_cnt[seg];
            float x[8]; float sum=0.f;
            #pragma unroll
            for (int i=0;i<8;i++){
                int j = lane + 32*i;
                x[i] = pos[(size_t)s*DD+j] + g_agg[(size_t)seg*DD+j] + cntf*b2[j];
                sum += x[i];
            }
            #pragma unroll
            for (int o=16;o;o>>=1) sum += __shfl_xor_sync(0xffffffffu,sum,o);
            float mu = sum*(1.0f/DD);
            float vs=0.f;
            #pragma unroll
            for (int i=0;i<8;i++){ float d2 = x[i]-mu; vs += d2*d2; }
            #pragma unroll
            for (int o=16;o;o>>=1) vs += __shfl_xor_sync(0xffffffffu,vs,o);
            float inv = rsqrtf(vs*(1.0f/DD)+1e-5f);
            #pragma unroll
            for (int i=0;i<8;i++){
                int j = lane+32*i;
                accp[i] += (x[i]-mu)*inv*lng[j] + lnb[j];
            }
        }
        float* sp = (float*)smr;
        if (tid < DD) sp[tid]=0.f;
        __syncthreads();
        #pragma unroll
        for (int i=0;i<8;i++) atomicAdd(&sp[lane+32*i], accp[i]);
        __syncthreads();
        if (tid < DD) atomicAdd(&g_pooled[bIdx*DD+tid], sp[tid]);
    }
    gsync();

    // ---------- Phase H: final MLP (16 blocks) ----------
    if (blk < BB){
        float* pp = (float*)smr;          // 256 floats
        float* hh = pp + DD;              // 512 floats
        if (tid < DD) pp[tid] = g_pooled[blk*DD+tid]*(1.0f/SS);
        __syncthreads();
        #pragma unroll
        for (int h=0; h<2; h++){
            int j = tid + h*NT;
            float s = bl1[j];
            #pragma unroll 4
            for (int k=0;k<DD;k++) s += pp[k]*Wl1[(size_t)k*DLAT+j];
            hh[j] = gelu_f(s);
        }
        __syncthreads();
        #pragma unroll
        for (int h=0; h<2; h++){
            int j = tid + h*NT;
            float o = bl2[j];
            #pragma unroll 4
            for (int k=0;k<DLAT;k++) o += hh[k]*Wl2[(size_t)k*DLAT+j];
            out[(size_t)blk*DLAT+j] = o;
        }
    }
}

extern "C" void kernel_launch(void* const* d_in, const int* in_sizes, int n_in,
                              void* d_out, int out_size){
    const int*   a0   = (const int*)d_in[0];
    const int*   a1   = (const int*)d_in[1];
    const int*   pidx = (const int*)d_in[2];
    const int*   ridx = (const int*)d_in[3];
    const float* pos  = (const float*)d_in[5];
    const float* pre  = (const float*)d_in[6];
    const float* rol  = (const float*)d_in[7];
    const float* W1   = (const float*)d_in[8];
    const float* b1   = (const float*)d_in[9];
    const float* W2   = (const float*)d_in[10];
    const float* b2   = (const float*)d_in[11];
    const float* lng  = (const float*)d_in[12];
    const float* lnb  = (const float*)d_in[13];
    const float* Wl1  = (const float*)d_in[14];
    const float* bl1  = (const float*)d_in[15];
    const float* Wl2  = (const float*)d_in[16];
    const float* bl2  = (const float*)d_in[17];
    float* out = (float*)d_out;

    k_fused<<<NB, NT>>>(a0, a1, pidx, ridx, pos, pre, rol,
                        W1, b1, W2, b2, lng, lnb, Wl1, bl1, Wl2, bl2, out);
}

// round 9
// speedup vs baseline: 1.7229x; 1.7229x over previous
#include <cuda_runtime.h>
#include <math.h>

#define BB 16
#define FF 2048
#define SS 512
#define DD 256
#define DH 512
#define NSEG (BB*SS)      // 8192
#define NEDGE (BB*FF)     // 32768
#define DLAT 512
#define NB 148            // co-resident blocks (<= SM count)
#define NT 512            // 16 warps/SM

typedef unsigned long long ull;

// ---- scratch (static __device__ arrays; no allocations allowed) ----
__device__ __align__(16) float g_P[2*SS*DH];     // [0]=pos@W1a, [1]=pos@W1c
__device__ __align__(16) float g_Eb[8*DH];       // pred_emb @ W1b
__device__ __align__(16) float g_Rc[8*DH];       // role_emb @ W1c
__device__ __align__(16) float g_H[NSEG*DH];     // per-node hidden sums
__device__ __align__(16) float g_agg[NSEG*DD];   // H @ W2
__device__ float g_pooled[BB*DD];
__device__ __align__(16) int g_cnt[NSEG];
__device__ int   g_off[NSEG];
__device__ int   g_run[NSEG];
__device__ unsigned g_perm[2*NEDGE];
// grid barrier state (monotonic tickets; never reset -> graph-replay-safe)
__device__ unsigned g_arrive_ctr = 0;
__device__ unsigned g_release_ctr = 0;

__device__ __forceinline__ float gelu_f(float x){
    return 0.5f*x*(1.0f + erff(x*0.70710678118654752440f));
}
__device__ __forceinline__ ull addf2(ull a, ull b){
    ull r; asm("add.rn.f32x2 %0, %1, %2;" : "=l"(r) : "l"(a), "l"(b)); return r;
}
__device__ __forceinline__ ull mulf2(ull a, ull b){
    ull r; asm("mul.rn.f32x2 %0, %1, %2;" : "=l"(r) : "l"(a), "l"(b)); return r;
}
__device__ __forceinline__ ull fmaf2_(ull a, ull b, ull c){
    ull r; asm("fma.rn.f32x2 %0, %1, %2, %3;" : "=l"(r) : "l"(a), "l"(b), "l"(c)); return r;
}
__device__ __forceinline__ void ffma2(ull &d, ull a, ull b){
    asm("fma.rn.f32x2 %0, %1, %2, %0;" : "+l"(d) : "l"(a), "l"(b));
}
__device__ __forceinline__ ull pack2(float x){
    ull r; asm("mov.b64 %0, {%1, %1};" : "=l"(r) : "f"(x)); return r;
}
__device__ __forceinline__ void unpack2(float &lo, float &hi, ull v){
    asm("mov.b64 {%0, %1}, %2;" : "=f"(lo), "=f"(hi) : "l"(v));
}

// ---- software grid barrier (all NB blocks co-resident) ----
__device__ __forceinline__ void gsync(){
    __threadfence();                 // release (gpu scope)
    __syncthreads();
    if (threadIdx.x == 0){
        unsigned t = atomicAdd(&g_arrive_ctr, 1u) + 1u;
        if ((t % NB) == 0u){
            atomicAdd(&g_release_ctr, 1u);
        } else {
            unsigned target = (t + NB - 1u) / NB;
            volatile unsigned* rel = &g_release_ctr;
            while (*rel < target) { __nanosleep(64); }
        }
    }
    __syncthreads();
    __threadfence();                 // acquire (CCTL.IVALL)
}

struct SmGemm { float As[2][16][132]; float Bs[2][16][128]; };  // 33280 B

__global__ __launch_bounds__(NT, 1)
void k_fused(const int* __restrict__ a0, const int* __restrict__ a1,
             const int* __restrict__ pidx, const int* __restrict__ ridx,
             const float* __restrict__ pos, const float* __restrict__ pre,
             const float* __restrict__ rol,
             const float* __restrict__ W1, const float* __restrict__ b1,
             const float* __restrict__ W2, const float* __restrict__ b2,
             const float* __restrict__ lng, const float* __restrict__ lnb,
             const float* __restrict__ Wl1, const float* __restrict__ bl1,
             const float* __restrict__ Wl2, const float* __restrict__ bl2,
             float* __restrict__ out){
    __shared__ __align__(16) char smr[sizeof(SmGemm)];
    int blk = blockIdx.x, tid = threadIdx.x;
    int gid = blk*NT + tid;

    // ---------- Phase A: zero cnt + pooled ----------
    if (gid < NSEG)  g_cnt[gid] = 0;
    if (gid < BB*DD) g_pooled[gid] = 0.f;
    gsync();

    // ---------- Phase B: count messages per destination ----------
    if (gid < NEDGE){
        int e = gid;
        int b = e >> 11;
        int v0 = a0[e], v1 = a1[e], p = pidx[e];
        bool role = (p == 1);
        int dstf = role ? v0 : v1;
        atomicAdd(&g_cnt[b*SS + dstf], 1);
        if (!role && p != 0) atomicAdd(&g_cnt[b*SS + v0], 1);
    }
    gsync();

    // ---------- Phase C: scan (block 0)  ||  precompute tables (blocks 1..144) ----------
    if (blk == 0){
        // exclusive scan of 8192 counts: 512 thr x 16 elems
        int base = tid*16;
        int s = 0;
        #pragma unroll 4
        for (int i=0;i<16;i++) s += g_cnt[base+i];
        int lane = tid&31, warp = tid>>5;
        int x = s;
        #pragma unroll
        for (int o=1;o<32;o<<=1){ int y=__shfl_up_sync(0xffffffffu,x,o); if(lane>=o) x+=y; }
        int* wsum = (int*)smr;
        if (lane==31) wsum[warp] = x;
        __syncthreads();
        int wb = 0;
        for (int w=0; w<warp; w++) wb += wsum[w];
        int run = x - s + wb;
        #pragma unroll 4
        for (int i=0;i<16;i++){
            g_off[base+i] = run; g_run[base+i] = run;
            run += g_cnt[base+i];
        }
    } else if (blk <= 128){
        // pos precompute tile 64x64 with 512 threads
        int w = blk - 1;                      // 0..127
        int nx = w&7, my = (w>>3)&7, z = w>>6;
        const float* Bm = W1 + (z ? (size_t)2*DD*DH : 0);
        float* C = g_P + (size_t)z * SS*DH;
        float (*As)[68] = (float(*)[68])smr;
        float (*Bs)[64] = (float(*)[64])(smr + 16*68*4);
        int bm = my*64, bn = nx*64;
        int ty = tid >> 4, tx = tid & 15;     // 2x4 per thread
        float acc[2][4] = {};
        for (int k0=0;k0<DD;k0+=16){
            #pragma unroll
            for (int h=0; h<2; h++){
                int i = tid + h*NT;           // 0..1023
                int m_ = i>>4, kl = i&15;
                As[kl][m_] = pos[(size_t)(bm+m_)*DD + k0 + kl];
                int kb = i>>6, nn = i&63;
                Bs[kb][nn] = Bm[(size_t)(k0+kb)*DH + bn + nn];
            }
            __syncthreads();
            #pragma unroll
            for (int k=0;k<16;k++){
                float av0 = As[k][ty*2], av1 = As[k][ty*2+1];
                float bv[4];
                #pragma unroll
                for (int j=0;j<4;j++) bv[j]=Bs[k][tx*4+j];
                #pragma unroll
                for (int j=0;j<4;j++){ acc[0][j] += av0*bv[j]; acc[1][j] += av1*bv[j]; }
            }
            __syncthreads();
        }
        #pragma unroll
        for (int i=0;i<2;i++)
            #pragma unroll
            for (int j=0;j<4;j++)
                C[(size_t)(bm+ty*2+i)*DH + bn+tx*4+j] = acc[i][j];
    } else if (blk <= 144){
        // small table row (16 rows): all 512 threads, j = tid
        int r8 = blk - 129;
        const float* A; const float* W; float* C; int r;
        if (r8 < 8){ A=pre; W=W1+DD*DH;   C=g_Eb; r=r8; }
        else       { A=rol; W=W1+2*DD*DH; C=g_Rc; r=r8-8; }
        float* a = (float*)smr;
        if (tid < DD) a[tid] = A[r*DD + tid];
        __syncthreads();
        float s = 0.f;
        #pragma unroll 4
        for (int k=0;k<DD;k++) s += a[k]*W[(size_t)k*DH + tid];
        C[r*DH + tid] = s;
    }
    gsync();

    // ---------- Phase D: place descriptors into CSR slots ----------
    if (gid < NEDGE){
        int e = gid;
        int b = e >> 11;
        int v0=a0[e], v1=a1[e], p=pidx[e];
        bool role = (p==1);
        unsigned descf; int dstf;
        if (role){ dstf=v0; descf=(unsigned)v0 | ((unsigned)(ridx[e]+1)<<10) | ((unsigned)p<<20) | (1u<<23); }
        else     { dstf=v1; descf=(unsigned)v0 | ((unsigned)v1<<10)          | ((unsigned)p<<20); }
        int slot = atomicAdd(&g_run[b*SS+dstf],1);
        g_perm[slot]=descf;
        if (!role && p!=0){
            unsigned descb = (unsigned)v1 | ((unsigned)v0<<10) | ((unsigned)p<<20);
            slot = atomicAdd(&g_run[b*SS+v0],1);
            g_perm[slot]=descb;
        }
    }
    gsync();

    // ---------- Phase E: gather with packed polynomial gelu (4 nodes/block-iter) ----------
    {
        int sub = tid >> 7;                   // 0..3
        int wg  = tid & 127;
        const ulonglong2* PA = reinterpret_cast<const ulonglong2*>(g_P);
        const ulonglong2* PC = PA + (size_t)SS*DH/4;
        const ulonglong2* EB = reinterpret_cast<const ulonglong2*>(g_Eb);
        const ulonglong2* RC = reinterpret_cast<const ulonglong2*>(g_Rc);
        ulonglong2 bv2 = reinterpret_cast<const ulonglong2*>(b1)[wg];
        const ull kC6 = pack2(-2.9761905e-3f);   // -1/336
        const ull kC4 = pack2( 2.5e-2f);         //  1/40
        const ull kC2 = pack2(-1.6666667e-1f);   // -1/6
        const ull kONE= pack2(1.0f);
        const ull kHA = pack2(0.3989422804f);    // 0.5*sqrt(2/pi)
        const ull kHALF=pack2(0.5f);

        for (int base = blk*4; base < NSEG; base += NB*4){
            int node = base + sub;
            int start = g_off[node];
            int cnt = g_cnt[node];
            ull aLo0=0, aHi0=0, aLo1=0, aHi1=0;
            int m = 0;
            #define GELU_ACC(uLo,uHi,accLo,accHi) do{ \
                ull x2 = mulf2(uLo,uLo); \
                ull p_ = fmaf2_(x2, kC6, kC4); p_ = fmaf2_(x2, p_, kC2); p_ = fmaf2_(x2, p_, kONE); \
                accLo = fmaf2_(mulf2(x2,p_), kHA, accLo); accLo = fmaf2_(uLo, kHALF, accLo); \
                ull y2 = mulf2(uHi,uHi); \
                ull q_ = fmaf2_(y2, kC6, kC4); q_ = fmaf2_(y2, q_, kC2); q_ = fmaf2_(y2, q_, kONE); \
                accHi = fmaf2_(mulf2(y2,q_), kHA, accHi); accHi = fmaf2_(uHi, kHALF, accHi); \
            }while(0)
            for (; m+2<=cnt; m+=2){
                unsigned d0 = g_perm[start+m], d1 = g_perm[start+m+1];
                int iA0 = d0 & 1023, iC0 = (d0>>10)&1023, p0 = (d0>>20)&7;
                int iA1 = d1 & 1023, iC1 = (d1>>10)&1023, p1 = (d1>>20)&7;
                const ulonglong2* T0 = (d0 & (1u<<23)) ? RC : PC;
                const ulonglong2* T1 = (d1 & (1u<<23)) ? RC : PC;
                ulonglong2 a0v = PA[(size_t)iA0*128 + wg];
                ulonglong2 c0v = T0[(size_t)iC0*128 + wg];
                ulonglong2 e0v = EB[(size_t)p0 *128 + wg];
                ulonglong2 a1v = PA[(size_t)iA1*128 + wg];
                ulonglong2 c1v = T1[(size_t)iC1*128 + wg];
                ulonglong2 e1v = EB[(size_t)p1 *128 + wg];
                ull uLo = addf2(addf2(a0v.x, c0v.x), addf2(e0v.x, bv2.x));
                ull uHi = addf2(addf2(a0v.y, c0v.y), addf2(e0v.y, bv2.y));
                GELU_ACC(uLo, uHi, aLo0, aHi0);
                ull vLo = addf2(addf2(a1v.x, c1v.x), addf2(e1v.x, bv2.x));
                ull vHi = addf2(addf2(a1v.y, c1v.y), addf2(e1v.y, bv2.y));
                GELU_ACC(vLo, vHi, aLo1, aHi1);
            }
            if (m < cnt){
                unsigned d0 = g_perm[start+m];
                int iA0 = d0 & 1023, iC0 = (d0>>10)&1023, p0 = (d0>>20)&7;
                const ulonglong2* T0 = (d0 & (1u<<23)) ? RC : PC;
                ulonglong2 a0v = PA[(size_t)iA0*128 + wg];
                ulonglong2 c0v = T0[(size_t)iC0*128 + wg];
                ulonglong2 e0v = EB[(size_t)p0 *128 + wg];
                ull uLo = addf2(addf2(a0v.x, c0v.x), addf2(e0v.x, bv2.x));
                ull uHi = addf2(addf2(a0v.y, c0v.y), addf2(e0v.y, bv2.y));
                GELU_ACC(uLo, uHi, aLo0, aHi0);
            }
            #undef GELU_ACC
            ulonglong2 res;
            res.x = addf2(aLo0, aLo1);
            res.y = addf2(aHi0, aHi1);
            reinterpret_cast<ulonglong2*>(g_H)[(size_t)node*128 + wg] = res;
        }
    }
    gsync();

    // ---------- Phase F: agg = H @ W2 (128x128 tiles, 8x4/thread, 128 blocks) ----------
    if (blk < 128){
        SmGemm* sg = (SmGemm*)smr;
        const float* A = g_H; const float* B = W2; float* C = g_agg;
        const int N = DD, K = DH;
        int bm = (blk>>1)*128, bn = (blk&1)*128;
        int ty = tid >> 5, tx = tid & 31;        // rows ty*8.., cols tx*4..

        int ar = tid>>2, ac = tid&3;             // A loader: 512 float4
        int br = tid>>5, bc = tid&31;            // B loader: 512 float4

        float4 pa = *reinterpret_cast<const float4*>(&A[(size_t)(bm+ar)*K + ac*4]);
        float4 pb = *reinterpret_cast<const float4*>(&B[(size_t)(br)*N + bn + bc*4]);

        ull acc2[4][4];
        #pragma unroll
        for (int i=0;i<4;i++)
            #pragma unroll
            for (int j=0;j<4;j++) acc2[i][j]=0ull;

        int buf = 0;
        sg->As[0][ac*4+0][ar]=pa.x; sg->As[0][ac*4+1][ar]=pa.y;
        sg->As[0][ac*4+2][ar]=pa.z; sg->As[0][ac*4+3][ar]=pa.w;
        *reinterpret_cast<float4*>(&sg->Bs[0][br][bc*4]) = pb;
        __syncthreads();

        const int ktiles = K/16;
        for (int kt=0; kt<ktiles; kt++){
            bool more = (kt+1 < ktiles);
            if (more){
                int kk = (kt+1)*16;
                pa = *reinterpret_cast<const float4*>(&A[(size_t)(bm+ar)*K + kk + ac*4]);
                pb = *reinterpret_cast<const float4*>(&B[(size_t)(kk+br)*N + bn + bc*4]);
            }
            #pragma unroll
            for (int k=0;k<16;k++){
                const ull* a64 = reinterpret_cast<const ull*>(&sg->As[buf][k][ty*8]);
                ull ap0=a64[0], ap1=a64[1], ap2=a64[2], ap3=a64[3];
                const float4* b4 = reinterpret_cast<const float4*>(&sg->Bs[buf][k][tx*4]);
                float4 bf = b4[0];
                float bv[4] = {bf.x,bf.y,bf.z,bf.w};
                #pragma unroll
                for (int j=0;j<4;j++){
                    ull bb = pack2(bv[j]);
                    ffma2(acc2[0][j], ap0, bb);
                    ffma2(acc2[1][j], ap1, bb);
                    ffma2(acc2[2][j], ap2, bb);
                    ffma2(acc2[3][j], ap3, bb);
                }
            }
            if (more){
                buf ^= 1;
                sg->As[buf][ac*4+0][ar]=pa.x; sg->As[buf][ac*4+1][ar]=pa.y;
                sg->As[buf][ac*4+2][ar]=pa.z; sg->As[buf][ac*4+3][ar]=pa.w;
                *reinterpret_cast<float4*>(&sg->Bs[buf][br][bc*4]) = pb;
                __syncthreads();
            }
        }
        #pragma unroll
        for (int i2=0;i2<4;i2++){
            float lo[4], hi[4];
            #pragma unroll
            for (int j=0;j<4;j++) unpack2(lo[j], hi[j], acc2[i2][j]);
            size_t r0 = (size_t)(bm + ty*8 + i2*2)*N + bn + tx*4;
            size_t r1 = r0 + N;
            *reinterpret_cast<float4*>(&C[r0]) = make_float4(lo[0],lo[1],lo[2],lo[3]);
            *reinterpret_cast<float4*>(&C[r1]) = make_float4(hi[0],hi[1],hi[2],hi[3]);
        }
    }
    gsync();

    // ---------- Phase G: LN + pooled accumulation (128 blocks, 16 warps each) ----------
    if (blk < 128){
        int bIdx = blk >> 3;
        int r0 = (blk & 7)*64;
        int warp = tid>>5, lane = tid&31;
        float accp[8];
        #pragma unroll
        for (int i=0;i<8;i++) accp[i]=0.f;
        for (int rr=warp; rr<64; rr+=16){
            int s = r0+rr;
            int seg = bIdx*SS + s;
            float cntf = (float)g_cnt[seg];
            float x[8]; float sum=0.f;
            #pragma unroll
            for (int i=0;i<8;i++){
                int j = lane + 32*i;
                x[i] = pos[(size_t)s*DD+j] + g_agg[(size_t)seg*DD+j] + cntf*b2[j];
                sum += x[i];
            }
            #pragma unroll
            for (int o=16;o;o>>=1) sum += __shfl_xor_sync(0xffffffffu,sum,o);
            float mu = sum*(1.0f/DD);
            float vs=0.f;
            #pragma unroll
            for (int i=0;i<8;i++){ float d2 = x[i]-mu; vs += d2*d2; }
            #pragma unroll
            for (int o=16;o;o>>=1) vs += __shfl_xor_sync(0xffffffffu,vs,o);
            float inv = rsqrtf(vs*(1.0f/DD)+1e-5f);
            #pragma unroll
            for (int i=0;i<8;i++){
                int j = lane+32*i;
                accp[i] += (x[i]-mu)*inv*lng[j] + lnb[j];
            }
        }
        float* sp = (float*)smr;
        if (tid < DD) sp[tid]=0.f;
        __syncthreads();
        #pragma unroll
        for (int i=0;i<8;i++) atomicAdd(&sp[lane+32*i], accp[i]);
        __syncthreads();
        if (tid < DD) atomicAdd(&g_pooled[bIdx*DD+tid], sp[tid]);
    }
    gsync();

    // ---------- Phase H: final MLP (16 blocks, 512 threads) ----------
    if (blk < BB){
        float* pp = (float*)smr;          // 256 floats
        float* hh = pp + DD;              // 512 floats
        if (tid < DD) pp[tid] = g_pooled[blk*DD+tid]*(1.0f/SS);
        __syncthreads();
        {
            int j = tid;
            float s = bl1[j];
            #pragma unroll 4
            for (int k=0;k<DD;k++) s += pp[k]*Wl1[(size_t)k*DLAT+j];
            hh[j] = gelu_f(s);
        }
        __syncthreads();
        {
            int j = tid;
            float o = bl2[j];
            #pragma unroll 4
            for (int k=0;k<DLAT;k++) o += hh[k]*Wl2[(size_t)k*DLAT+j];
            out[(size_t)blk*DLAT+j] = o;
        }
    }
}

extern "C" void kernel_launch(void* const* d_in, const int* in_sizes, int n_in,
                              void* d_out, int out_size){
    const int*   a0   = (const int*)d_in[0];
    const int*   a1   = (const int*)d_in[1];
    const int*   pidx = (const int*)d_in[2];
    const int*   ridx = (const int*)d_in[3];
    const float* pos  = (const float*)d_in[5];
    const float* pre  = (const float*)d_in[6];
    const float* rol  = (const float*)d_in[7];
    const float* W1   = (const float*)d_in[8];
    const float* b1   = (const float*)d_in[9];
    const float* W2   = (const float*)d_in[10];
    const float* b2   = (const float*)d_in[11];
    const float* lng  = (const float*)d_in[12];
    const float* lnb  = (const float*)d_in[13];
    const float* Wl1  = (const float*)d_in[14];
    const float* bl1  = (const float*)d_in[15];
    const float* Wl2  = (const float*)d_in[16];
    const float* bl2  = (const float*)d_in[17];
    float* out = (float*)d_out;

    k_fused<<<NB, NT>>>(a0, a1, pidx, ridx, pos, pre, rol,
                        W1, b1, W2, b2, lng, lnb, Wl1, bl1, Wl2, bl2, out);
}